// round 1
// baseline (speedup 1.0000x reference)
#include <cuda_runtime.h>
#include <math.h>

#define Bq 8
#define Nq 1024
#define Cq 512
#define Hq 4
#define HDq 128
// SCALE = 1/sqrt(128)
#define SCALEq 0.08838834764831845f

// ---------------- scratch (static __device__, allocation-free) ----------------
__device__ float g_q[Bq * Hq * Nq * HDq];   // 16.8 MB
__device__ float g_k[Bq * Hq * Nq * HDq];   // 16.8 MB
__device__ float g_v[Bq * Hq * Nq * HDq];   // 16.8 MB
__device__ float g_s[(size_t)Bq * Hq * Nq * Nq]; // 134 MB (scores, then probs in place)
__device__ float g_y[Bq * Nq * Cq];         // 16.8 MB (pre-projection)

// ---------------- GEMM cores ----------------
// C_tile(64x64) = A(64xK, row-major) * B(64xK, row-major)^T
// A points at row0*K, Bm points at col0*K. 256 threads, 4x4 per thread.
template <int K>
__device__ __forceinline__ void gemm_abt_core(const float* __restrict__ A,
                                              const float* __restrict__ Bm,
                                              float acc[4][4]) {
    __shared__ float As[64][17];
    __shared__ float Bs[64][17];
    const int tid = threadIdx.x;
    const int ar = tid >> 2;          // 0..63
    const int ac = (tid & 3) * 4;     // 0,4,8,12
    const int ty = tid >> 4;          // 0..15
    const int tx = tid & 15;          // 0..15

    for (int k0 = 0; k0 < K; k0 += 16) {
        float4 av = *(const float4*)(A + ar * K + k0 + ac);
        float4 bv = *(const float4*)(Bm + ar * K + k0 + ac);
        As[ar][ac + 0] = av.x; As[ar][ac + 1] = av.y;
        As[ar][ac + 2] = av.z; As[ar][ac + 3] = av.w;
        Bs[ar][ac + 0] = bv.x; Bs[ar][ac + 1] = bv.y;
        Bs[ar][ac + 2] = bv.z; Bs[ar][ac + 3] = bv.w;
        __syncthreads();
#pragma unroll
        for (int kk = 0; kk < 16; kk++) {
            float a[4], b[4];
#pragma unroll
            for (int i = 0; i < 4; i++) a[i] = As[ty * 4 + i][kk];
#pragma unroll
            for (int j = 0; j < 4; j++) b[j] = Bs[tx * 4 + j][kk];
#pragma unroll
            for (int i = 0; i < 4; i++)
#pragma unroll
                for (int j = 0; j < 4; j++) acc[i][j] += a[i] * b[j];
        }
        __syncthreads();
    }
}

// C_tile(64x64) = A(64x1024, row-major, lda=1024) * B(1024x128, row-major, ldb=128)
// A points at row0*1024, Bm points at col0 (column offset applied).
__device__ __forceinline__ void gemm_ab_core_1024_128(const float* __restrict__ A,
                                                      const float* __restrict__ Bm,
                                                      float acc[4][4]) {
    __shared__ float As[64][17];
    __shared__ float Bs[16][68];
    const int tid = threadIdx.x;
    const int ar = tid >> 2;          // 0..63
    const int ac = (tid & 3) * 4;     // 0,4,8,12
    const int br = tid >> 4;          // 0..15
    const int bc = (tid & 15) * 4;    // 0..60
    const int ty = tid >> 4;
    const int tx = tid & 15;

    for (int k0 = 0; k0 < 1024; k0 += 16) {
        float4 av = *(const float4*)(A + ar * 1024 + k0 + ac);
        float4 bv = *(const float4*)(Bm + (size_t)(k0 + br) * HDq + bc);
        As[ar][ac + 0] = av.x; As[ar][ac + 1] = av.y;
        As[ar][ac + 2] = av.z; As[ar][ac + 3] = av.w;
        Bs[br][bc + 0] = bv.x; Bs[br][bc + 1] = bv.y;
        Bs[br][bc + 2] = bv.z; Bs[br][bc + 3] = bv.w;
        __syncthreads();
#pragma unroll
        for (int kk = 0; kk < 16; kk++) {
            float a[4], b[4];
#pragma unroll
            for (int i = 0; i < 4; i++) a[i] = As[ty * 4 + i][kk];
#pragma unroll
            for (int j = 0; j < 4; j++) b[j] = Bs[kk][tx * 4 + j];
#pragma unroll
            for (int i = 0; i < 4; i++)
#pragma unroll
                for (int j = 0; j < 4; j++) acc[i][j] += a[i] * b[j];
        }
        __syncthreads();
    }
}

// ---------------- kernels ----------------

// qkv = x @ w_qkv^T ; scatter into g_q/g_k/g_v with layout [B,H,N,HD]
__global__ void k_qkv(const float* __restrict__ X, const float* __restrict__ W) {
    const int row0 = blockIdx.y * 64;   // 0..8191 (b*N+n)
    const int col0 = blockIdx.x * 64;   // 0..1535
    float acc[4][4] = {};
    gemm_abt_core<Cq>(X + (size_t)row0 * Cq, W + (size_t)col0 * Cq, acc);

    // one 64-wide block lies entirely inside one (part, head) chunk
    const int part = col0 >> 9;          // 0=q,1=k,2=v
    const int rem  = col0 & 511;
    const int h    = rem >> 7;
    float* dst = (part == 0) ? g_q : (part == 1) ? g_k : g_v;

    const int ty = threadIdx.x >> 4, tx = threadIdx.x & 15;
#pragma unroll
    for (int i = 0; i < 4; i++) {
        const int r = row0 + ty * 4 + i;
        const int b = r >> 10, n = r & 1023;
        const size_t base = ((size_t)(b * Hq + h) * Nq + n) * HDq;
#pragma unroll
        for (int j = 0; j < 4; j++) {
            const int d = (col0 + tx * 4 + j) & 127;
            dst[base + d] = acc[i][j];
        }
    }
}

// S[z] = q[z] @ k[z]^T * scale, z = b*H+h
__global__ void k_scores() {
    const int z    = blockIdx.z;
    const int row0 = blockIdx.y * 64;
    const int col0 = blockIdx.x * 64;
    float acc[4][4] = {};
    const float* A  = g_q + (size_t)z * Nq * HDq + (size_t)row0 * HDq;
    const float* Bm = g_k + (size_t)z * Nq * HDq + (size_t)col0 * HDq;
    gemm_abt_core<HDq>(A, Bm, acc);

    float* S = g_s + (size_t)z * Nq * Nq;
    const int ty = threadIdx.x >> 4, tx = threadIdx.x & 15;
#pragma unroll
    for (int i = 0; i < 4; i++)
#pragma unroll
        for (int j = 0; j < 4; j++)
            S[(size_t)(row0 + ty * 4 + i) * Nq + col0 + tx * 4 + j] = acc[i][j] * SCALEq;
}

__device__ __forceinline__ float bred(float v, bool is_max, float* red) {
#pragma unroll
    for (int o = 16; o > 0; o >>= 1) {
        float t = __shfl_xor_sync(0xffffffffu, v, o);
        v = is_max ? fmaxf(v, t) : (v + t);
    }
    const int tid = threadIdx.x;
    if ((tid & 31) == 0) red[tid >> 5] = v;
    __syncthreads();
    if (tid == 0) {
        float r = red[0];
        for (int w = 1; w < 8; w++) r = is_max ? fmaxf(r, red[w]) : (r + red[w]);
        red[0] = r;
    }
    __syncthreads();
    float r = red[0];
    __syncthreads();
    return r;
}

// For each (b,n): mixed[i,:] = sum_h M[i,h] * S[b,h,n,:], softmax, write in place.
__global__ void k_mix_softmax(const float* __restrict__ w_main,
                              const float* __restrict__ w_rest) {
    __shared__ float s[Hq][Nq];   // 16 KB
    __shared__ float red[8];
    const int bn = blockIdx.x;
    const int b = bn >> 10, n = bn & 1023;
    const int tid = threadIdx.x;
    const size_t base = ((size_t)(b * Hq) * Nq + n) * Nq; // row (b, h=0, n); h stride = Nq*Nq
    const size_t hstride = (size_t)Nq * Nq;

    for (int idx = tid; idx < Hq * Nq; idx += 256) {
        const int h = idx >> 10, m = idx & 1023;
        s[h][m] = g_s[base + (size_t)h * hstride + m];
    }
    __syncthreads();

    // build mix matrix rows
    float Mr[Hq][Hq];
#pragma unroll
    for (int i = 0; i < Hq; i++) {
#pragma unroll
        for (int j = 0; j < Hq; j++) {
            if (j == i) Mr[i][j] = w_main[i];
            else        Mr[i][j] = w_rest[i * (Hq - 1) + j - (j > i ? 1 : 0)];
        }
    }

    for (int i = 0; i < Hq; i++) {
        float v[4];
        float lmax = -INFINITY;
#pragma unroll
        for (int t = 0; t < 4; t++) {
            const int m = tid + t * 256;
            float val = Mr[i][0] * s[0][m] + Mr[i][1] * s[1][m]
                      + Mr[i][2] * s[2][m] + Mr[i][3] * s[3][m];
            v[t] = val;
            lmax = fmaxf(lmax, val);
        }
        const float gmax = bred(lmax, true, red);
        float lsum = 0.f;
#pragma unroll
        for (int t = 0; t < 4; t++) {
            v[t] = __expf(v[t] - gmax);
            lsum += v[t];
        }
        const float gsum = bred(lsum, false, red);
        const float inv = 1.f / gsum;
#pragma unroll
        for (int t = 0; t < 4; t++)
            g_s[base + (size_t)i * hstride + tid + t * 256] = v[t] * inv;
        __syncthreads();
    }
}

// out[z] = P[z] @ V[z], scatter into g_y[b, n, h*HD + d]
__global__ void k_pv() {
    const int z    = blockIdx.z;
    const int row0 = blockIdx.y * 64;   // n
    const int col0 = blockIdx.x * 64;   // d (0 or 64)
    float acc[4][4] = {};
    const float* A  = g_s + (size_t)z * Nq * Nq + (size_t)row0 * Nq;
    const float* Bm = g_v + (size_t)z * Nq * HDq + col0;
    gemm_ab_core_1024_128(A, Bm, acc);

    const int b = z >> 2, h = z & 3;
    const int ty = threadIdx.x >> 4, tx = threadIdx.x & 15;
#pragma unroll
    for (int i = 0; i < 4; i++) {
        const int n = row0 + ty * 4 + i;
        const size_t base = ((size_t)b * Nq + n) * Cq + h * HDq;
#pragma unroll
        for (int j = 0; j < 4; j++)
            g_y[base + col0 + tx * 4 + j] = acc[i][j];
    }
}

// out = y @ w_proj^T + b_proj
__global__ void k_proj(const float* __restrict__ Wp, const float* __restrict__ bias,
                       float* __restrict__ out) {
    const int row0 = blockIdx.y * 64;
    const int col0 = blockIdx.x * 64;
    float acc[4][4] = {};
    gemm_abt_core<Cq>(g_y + (size_t)row0 * Cq, Wp + (size_t)col0 * Cq, acc);

    const int ty = threadIdx.x >> 4, tx = threadIdx.x & 15;
#pragma unroll
    for (int i = 0; i < 4; i++) {
        const int r = row0 + ty * 4 + i;
#pragma unroll
        for (int j = 0; j < 4; j++) {
            const int c = col0 + tx * 4 + j;
            out[(size_t)r * Cq + c] = acc[i][j] + bias[c];
        }
    }
}

// ---------------- launch ----------------
extern "C" void kernel_launch(void* const* d_in, const int* in_sizes, int n_in,
                              void* d_out, int out_size) {
    const float* x      = (const float*)d_in[0];
    const float* w_qkv  = (const float*)d_in[1];
    const float* w_proj = (const float*)d_in[2];
    const float* b_proj = (const float*)d_in[3];
    const float* w_main = (const float*)d_in[4];
    const float* w_rest = (const float*)d_in[5];
    float* out = (float*)d_out;

    dim3 blk(256);
    // qkv: [8192 x 1536 x 512]
    k_qkv<<<dim3(1536 / 64, (Bq * Nq) / 64), blk>>>(x, w_qkv);
    // scores: 32 x [1024 x 1024 x 128]
    k_scores<<<dim3(Nq / 64, Nq / 64, Bq * Hq), blk>>>();
    // mix + softmax (in place on g_s)
    k_mix_softmax<<<Bq * Nq, blk>>>(w_main, w_rest);
    // P @ V: 32 x [1024 x 128 x 1024]
    k_pv<<<dim3(HDq / 64, Nq / 64, Bq * Hq), blk>>>();
    // projection: [8192 x 512 x 512] + bias
    k_proj<<<dim3(Cq / 64, (Bq * Nq) / 64), blk>>>(w_proj, b_proj, out);
}

// round 4
// speedup vs baseline: 2.3647x; 2.3647x over previous
#include <cuda_runtime.h>
#include <math.h>

#define Bq 8
#define Nq 1024
#define Cq 512
#define Hq 4
#define HDq 128
#define SCALEq 0.08838834764831845f

// ---------------- scratch ----------------
__device__ float g_q[Bq * Hq * Nq * HDq];
__device__ float g_k[Bq * Hq * Nq * HDq];
__device__ float g_v[Bq * Hq * Nq * HDq];
__device__ float g_s[(size_t)Bq * Hq * Nq * Nq]; // scores then probs (in place)
__device__ float g_y[Bq * Nq * Cq];

// ---------------- tf32 helpers ----------------
__device__ __forceinline__ unsigned f2tf(float f) {
    unsigned r;
    asm("cvt.rna.tf32.f32 %0, %1;" : "=r"(r) : "f"(f));
    return r;
}
__device__ __forceinline__ float tfr(float f) { return __uint_as_float(f2tf(f)); }

__device__ __forceinline__ void mma8(float c[4], const unsigned a[4], const unsigned b[2]) {
    asm volatile(
        "mma.sync.aligned.m16n8k8.row.col.f32.tf32.tf32.f32 "
        "{%0,%1,%2,%3},{%4,%5,%6,%7},{%8,%9},{%0,%1,%2,%3};"
        : "+f"(c[0]), "+f"(c[1]), "+f"(c[2]), "+f"(c[3])
        : "r"(a[0]), "r"(a[1]), "r"(a[2]), "r"(a[3]), "r"(b[0]), "r"(b[1]));
}

// ================= MMA core: C(128x64) = A(128xK) * B(64xK)^T =================
// A points at block row0*lda, B at block col0*ldb. 128 threads, 4 warps (2x2),
// warp tile 64x32 = 4x4 m16n8k8 tiles. Smem stride 20 -> conflict-free frags.
template <int K, bool CVTA, bool CVTB>
__device__ __forceinline__ void mma_abt(const float* __restrict__ A, int lda,
                                        const float* __restrict__ B, int ldb,
                                        float c[4][4][4]) {
    __shared__ float As[128][20];
    __shared__ float Bs[64][20];
    const int tid = threadIdx.x;
    const int lane = tid & 31;
    const int wid = tid >> 5;
    const int wm = (wid >> 1) * 64;
    const int wn = (wid & 1) * 32;
    const int lr = lane >> 2;   // 0..7
    const int lc = lane & 3;    // 0..3

    for (int k0 = 0; k0 < K; k0 += 16) {
#pragma unroll
        for (int i = 0; i < 4; i++) {
            int li = tid + i * 128;
            int r = li >> 2, c4 = (li & 3) * 4;
            float4 v = *(const float4*)(A + (size_t)r * lda + k0 + c4);
            if (CVTA) { v.x = tfr(v.x); v.y = tfr(v.y); v.z = tfr(v.z); v.w = tfr(v.w); }
            As[r][c4 + 0] = v.x; As[r][c4 + 1] = v.y;
            As[r][c4 + 2] = v.z; As[r][c4 + 3] = v.w;
        }
#pragma unroll
        for (int i = 0; i < 2; i++) {
            int li = tid + i * 128;
            int r = li >> 2, c4 = (li & 3) * 4;
            float4 v = *(const float4*)(B + (size_t)r * ldb + k0 + c4);
            if (CVTB) { v.x = tfr(v.x); v.y = tfr(v.y); v.z = tfr(v.z); v.w = tfr(v.w); }
            Bs[r][c4 + 0] = v.x; Bs[r][c4 + 1] = v.y;
            Bs[r][c4 + 2] = v.z; Bs[r][c4 + 3] = v.w;
        }
        __syncthreads();
#pragma unroll
        for (int kk = 0; kk < 16; kk += 8) {
            unsigned a[4][4], b[4][2];
#pragma unroll
            for (int t = 0; t < 4; t++) {
                a[t][0] = __float_as_uint(As[wm + t * 16 + lr][kk + lc]);
                a[t][1] = __float_as_uint(As[wm + t * 16 + 8 + lr][kk + lc]);
                a[t][2] = __float_as_uint(As[wm + t * 16 + lr][kk + lc + 4]);
                a[t][3] = __float_as_uint(As[wm + t * 16 + 8 + lr][kk + lc + 4]);
            }
#pragma unroll
            for (int u = 0; u < 4; u++) {
                b[u][0] = __float_as_uint(Bs[wn + u * 8 + lr][kk + lc]);
                b[u][1] = __float_as_uint(Bs[wn + u * 8 + lr][kk + lc + 4]);
            }
#pragma unroll
            for (int t = 0; t < 4; t++)
#pragma unroll
                for (int u = 0; u < 4; u++) mma8(c[t][u], a[t], b[u]);
        }
        __syncthreads();
    }
}

// ======== MMA core: C(128x64) = A(128x1024) * B(1024x64), B row-major k x n ====
// B points at n-column offset; ldb applies to k rows. Transposed smem fill.
__device__ __forceinline__ void mma_ab_pv(const float* __restrict__ A,
                                          const float* __restrict__ B, int ldb,
                                          float c[4][4][4]) {
    __shared__ float As[128][20];
    __shared__ float Bs[64][20];
    const int tid = threadIdx.x;
    const int lane = tid & 31;
    const int wid = tid >> 5;
    const int wm = (wid >> 1) * 64;
    const int wn = (wid & 1) * 32;
    const int lr = lane >> 2;
    const int lc = lane & 3;

    for (int k0 = 0; k0 < 1024; k0 += 16) {
#pragma unroll
        for (int i = 0; i < 4; i++) {
            int li = tid + i * 128;
            int r = li >> 2, c4 = (li & 3) * 4;
            float4 v = *(const float4*)(A + (size_t)r * 1024 + k0 + c4);
            As[r][c4 + 0] = v.x; As[r][c4 + 1] = v.y;
            As[r][c4 + 2] = v.z; As[r][c4 + 3] = v.w;
        }
        // B tile: 16 k-rows x 64 n-cols; coalesced loads, transposed store
#pragma unroll
        for (int i = 0; i < 8; i++) {
            int li = tid + i * 128;          // 0..1023
            int k = li >> 6, n = li & 63;
            Bs[n][k] = B[(size_t)(k0 + k) * ldb + n];
        }
        __syncthreads();
#pragma unroll
        for (int kk = 0; kk < 16; kk += 8) {
            unsigned a[4][4], b[4][2];
#pragma unroll
            for (int t = 0; t < 4; t++) {
                a[t][0] = __float_as_uint(As[wm + t * 16 + lr][kk + lc]);
                a[t][1] = __float_as_uint(As[wm + t * 16 + 8 + lr][kk + lc]);
                a[t][2] = __float_as_uint(As[wm + t * 16 + lr][kk + lc + 4]);
                a[t][3] = __float_as_uint(As[wm + t * 16 + 8 + lr][kk + lc + 4]);
            }
#pragma unroll
            for (int u = 0; u < 4; u++) {
                b[u][0] = __float_as_uint(Bs[wn + u * 8 + lr][kk + lc]);
                b[u][1] = __float_as_uint(Bs[wn + u * 8 + lr][kk + lc + 4]);
            }
#pragma unroll
            for (int t = 0; t < 4; t++)
#pragma unroll
                for (int u = 0; u < 4; u++) mma8(c[t][u], a[t], b[u]);
        }
        __syncthreads();
    }
}

// ---------------- kernels ----------------

// qkv = x @ w_qkv^T ; scatter pre-rounded tf32 into g_q/g_k/g_v [B,H,N,HD]
__global__ void k_qkv(const float* __restrict__ X, const float* __restrict__ W) {
    const int row0 = blockIdx.y * 128;   // b*N+n
    const int col0 = blockIdx.x * 64;    // 0..1535
    float c[4][4][4] = {};
    mma_abt<Cq, true, true>(X + (size_t)row0 * Cq, Cq, W + (size_t)col0 * Cq, Cq, c);

    const int part = col0 >> 9;
    const int h = (col0 & 511) >> 7;
    const int d0 = col0 & 127;
    float* dst = (part == 0) ? g_q : (part == 1) ? g_k : g_v;

    const int tid = threadIdx.x, lane = tid & 31, wid = tid >> 5;
    const int wm = (wid >> 1) * 64, wn = (wid & 1) * 32;
    const int lr = lane >> 2, lc = lane & 3;
#pragma unroll
    for (int t = 0; t < 4; t++) {
#pragma unroll
        for (int u = 0; u < 4; u++) {
            const int d = d0 + wn + u * 8 + 2 * lc;
#pragma unroll
            for (int half = 0; half < 2; half++) {
                const int r = row0 + wm + t * 16 + lr + half * 8;
                const int b = r >> 10, n = r & 1023;
                const size_t base = ((size_t)(b * Hq + h) * Nq + n) * HDq + d;
                dst[base]     = tfr(c[t][u][half * 2 + 0]);
                dst[base + 1] = tfr(c[t][u][half * 2 + 1]);
            }
        }
    }
}

// S[z] = q[z] @ k[z]^T (raw, scale folded into mix)
__global__ void k_scores() {
    const int z = blockIdx.z;
    const int row0 = blockIdx.y * 128;
    const int col0 = blockIdx.x * 64;
    float c[4][4][4] = {};
    const float* A = g_q + (size_t)z * Nq * HDq + (size_t)row0 * HDq;
    const float* B = g_k + (size_t)z * Nq * HDq + (size_t)col0 * HDq;
    mma_abt<HDq, false, false>(A, HDq, B, HDq, c);

    float* S = g_s + (size_t)z * Nq * Nq;
    const int tid = threadIdx.x, lane = tid & 31, wid = tid >> 5;
    const int wm = (wid >> 1) * 64, wn = (wid & 1) * 32;
    const int lr = lane >> 2, lc = lane & 3;
#pragma unroll
    for (int t = 0; t < 4; t++)
#pragma unroll
        for (int u = 0; u < 4; u++) {
            const int col = col0 + wn + u * 8 + 2 * lc;
#pragma unroll
            for (int half = 0; half < 2; half++) {
                const int r = row0 + wm + t * 16 + lr + half * 8;
                *(float2*)(S + (size_t)r * Nq + col) =
                    make_float2(c[t][u][half * 2 + 0], c[t][u][half * 2 + 1]);
            }
        }
}

__device__ __forceinline__ float bred(float v, bool is_max, float* red) {
#pragma unroll
    for (int o = 16; o > 0; o >>= 1) {
        float t = __shfl_xor_sync(0xffffffffu, v, o);
        v = is_max ? fmaxf(v, t) : (v + t);
    }
    const int tid = threadIdx.x;
    if ((tid & 31) == 0) red[tid >> 5] = v;
    __syncthreads();
    if (tid == 0) {
        float r = red[0];
        for (int w = 1; w < 8; w++) r = is_max ? fmaxf(r, red[w]) : (r + red[w]);
        red[0] = r;
    }
    __syncthreads();
    float r = red[0];
    __syncthreads();
    return r;
}

// per (b,n): mix heads with M*SCALE, softmax, write probs (tf32-rounded) in place
__global__ void k_mix_softmax(const float* __restrict__ w_main,
                              const float* __restrict__ w_rest) {
    __shared__ float s[Hq][Nq];
    __shared__ float red[8];
    const int bn = blockIdx.x;
    const int b = bn >> 10, n = bn & 1023;
    const int tid = threadIdx.x;
    const size_t base = ((size_t)(b * Hq) * Nq + n) * Nq;
    const size_t hstride = (size_t)Nq * Nq;

    for (int idx = tid; idx < Hq * Nq; idx += 256) {
        const int h = idx >> 10, m = idx & 1023;
        s[h][m] = g_s[base + (size_t)h * hstride + m];
    }
    __syncthreads();

    float Mr[Hq][Hq];
#pragma unroll
    for (int i = 0; i < Hq; i++)
#pragma unroll
        for (int j = 0; j < Hq; j++) {
            float w = (j == i) ? w_main[i] : w_rest[i * (Hq - 1) + j - (j > i ? 1 : 0)];
            Mr[i][j] = w * SCALEq;
        }

    for (int i = 0; i < Hq; i++) {
        float v[4];
        float lmax = -INFINITY;
#pragma unroll
        for (int t = 0; t < 4; t++) {
            const int m = tid + t * 256;
            float val = Mr[i][0] * s[0][m] + Mr[i][1] * s[1][m]
                      + Mr[i][2] * s[2][m] + Mr[i][3] * s[3][m];
            v[t] = val;
            lmax = fmaxf(lmax, val);
        }
        const float gmax = bred(lmax, true, red);
        float lsum = 0.f;
#pragma unroll
        for (int t = 0; t < 4; t++) {
            v[t] = __expf(v[t] - gmax);
            lsum += v[t];
        }
        const float gsum = bred(lsum, false, red);
        const float inv = 1.f / gsum;
#pragma unroll
        for (int t = 0; t < 4; t++)
            g_s[base + (size_t)i * hstride + tid + t * 256] = tfr(v[t] * inv);
        __syncthreads();
    }
}

// out[z] = P[z] @ V[z] -> g_y[b, n, h*HD + d] (tf32-rounded for proj)
__global__ void k_pv() {
    const int z = blockIdx.z;
    const int row0 = blockIdx.y * 128;  // n
    const int col0 = blockIdx.x * 64;   // d
    float c[4][4][4] = {};
    const float* A = g_s + (size_t)z * Nq * Nq + (size_t)row0 * Nq;
    const float* B = g_v + (size_t)z * Nq * HDq + col0;
    mma_ab_pv(A, B, HDq, c);

    const int b = z >> 2, h = z & 3;
    const int tid = threadIdx.x, lane = tid & 31, wid = tid >> 5;
    const int wm = (wid >> 1) * 64, wn = (wid & 1) * 32;
    const int lr = lane >> 2, lc = lane & 3;
#pragma unroll
    for (int t = 0; t < 4; t++)
#pragma unroll
        for (int u = 0; u < 4; u++) {
            const int d = col0 + wn + u * 8 + 2 * lc;
#pragma unroll
            for (int half = 0; half < 2; half++) {
                const int n = row0 + wm + t * 16 + lr + half * 8;
                const size_t base = ((size_t)b * Nq + n) * Cq + h * HDq + d;
                g_y[base]     = tfr(c[t][u][half * 2 + 0]);
                g_y[base + 1] = tfr(c[t][u][half * 2 + 1]);
            }
        }
}

// out = y @ w_proj^T + b_proj
__global__ void k_proj(const float* __restrict__ Wp, const float* __restrict__ bias,
                       float* __restrict__ out) {
    const int row0 = blockIdx.y * 128;
    const int col0 = blockIdx.x * 64;
    float c[4][4][4] = {};
    mma_abt<Cq, false, true>(g_y + (size_t)row0 * Cq, Cq, Wp + (size_t)col0 * Cq, Cq, c);

    const int tid = threadIdx.x, lane = tid & 31, wid = tid >> 5;
    const int wm = (wid >> 1) * 64, wn = (wid & 1) * 32;
    const int lr = lane >> 2, lc = lane & 3;
#pragma unroll
    for (int t = 0; t < 4; t++)
#pragma unroll
        for (int u = 0; u < 4; u++) {
            const int col = col0 + wn + u * 8 + 2 * lc;
            const float b0 = bias[col], b1 = bias[col + 1];
#pragma unroll
            for (int half = 0; half < 2; half++) {
                const int r = row0 + wm + t * 16 + lr + half * 8;
                *(float2*)(out + (size_t)r * Cq + col) =
                    make_float2(c[t][u][half * 2 + 0] + b0, c[t][u][half * 2 + 1] + b1);
            }
        }
}

// ---------------- launch ----------------
extern "C" void kernel_launch(void* const* d_in, const int* in_sizes, int n_in,
                              void* d_out, int out_size) {
    const float* x      = (const float*)d_in[0];
    const float* w_qkv  = (const float*)d_in[1];
    const float* w_proj = (const float*)d_in[2];
    const float* b_proj = (const float*)d_in[3];
    const float* w_main = (const float*)d_in[4];
    const float* w_rest = (const float*)d_in[5];
    float* out = (float*)d_out;

    dim3 blk(128);
    k_qkv<<<dim3(1536 / 64, (Bq * Nq) / 128), blk>>>(x, w_qkv);
    k_scores<<<dim3(Nq / 64, Nq / 128, Bq * Hq), blk>>>();
    k_mix_softmax<<<Bq * Nq, dim3(256)>>>(w_main, w_rest);
    k_pv<<<dim3(HDq / 64, Nq / 128, Bq * Hq), blk>>>();
    k_proj<<<dim3(Cq / 64, (Bq * Nq) / 128), blk>>>(w_proj, b_proj, out);
}